// round 2
// baseline (speedup 1.0000x reference)
#include <cuda_runtime.h>

#define NN 50000
#define FIN 128
#define HC  128          // H*C = 4*32
#define EE  800000
#define ET  850000       // EE + NN self loops
#define NEG_SLOPE 0.2f

// ---- scratch (static device globals; no runtime allocation) ----
__device__ float g_xl[NN * HC];      // x @ Wl
__device__ float g_xr[NN * HC];      // x @ Wr
__device__ int   g_deg[NN];
__device__ int   g_cur[NN];
__device__ int   g_off[NN + 1];
__device__ int   g_ssrc[ET];         // src node per CSR slot
__device__ int   g_seid[ET];         // original edge id per CSR slot
__device__ int   g_is64;             // edge_index dtype flag

// ---- probe: detect int64 vs int32 edge_index ----
__global__ void probe_kernel(const int* __restrict__ ei32) {
    if (threadIdx.x == 0 && blockIdx.x == 0) {
        int nonzero = 0;
        for (int i = 0; i < 64; i++) {
            long long k = ((long long)i * 1234567) % EE;   // spread samples
            int idx = (int)(2 * k + 1);                    // high word if int64
            if (ei32[idx] != 0) nonzero++;
        }
        g_is64 = (nonzero == 0) ? 1 : 0;
    }
}

__device__ __forceinline__ void load_edge(const void* ei, int e, int& src, int& dst) {
    if (e >= EE) { src = dst = e - EE; return; }
    if (g_is64) {
        const long long* p = (const long long*)ei;
        src = (int)p[e]; dst = (int)p[EE + e];
    } else {
        const int* p = (const int*)ei;
        src = p[e]; dst = p[EE + e];
    }
    src = min(max(src, 0), NN - 1);
    dst = min(max(dst, 0), NN - 1);
}

__global__ void zero_kernel() {
    int i = blockIdx.x * blockDim.x + threadIdx.x;
    if (i < NN) { g_deg[i] = 0; g_cur[i] = 0; }
}

// ---- 50000x128 @ 128x128 fp32 GEMM, 64-row x 128-col tile per block ----
__global__ void gemm_kernel(const float* __restrict__ x,
                            const float* __restrict__ W, int which) {
    __shared__ float Xs[64 * 32];
    __shared__ float Ws[32 * 128];
    float* out = which ? g_xr : g_xl;
    int tid = threadIdx.x;            // 256 threads
    int tx = tid & 31;                // column group (4 cols each)
    int ty = tid >> 5;                // row group (8 rows each)
    int row0 = blockIdx.x * 64;

    float4 acc[8];
#pragma unroll
    for (int r = 0; r < 8; r++) acc[r] = make_float4(0.f, 0.f, 0.f, 0.f);

    for (int k0 = 0; k0 < FIN; k0 += 32) {
#pragma unroll
        for (int i = 0; i < 8; i++) {
            int idx = i * 256 + tid;
            int r = idx >> 5, c = idx & 31;
            int rr = row0 + r; if (rr >= NN) rr = NN - 1;
            Xs[r * 32 + c] = x[rr * FIN + k0 + c];
        }
#pragma unroll
        for (int i = 0; i < 16; i++) {
            int idx = i * 256 + tid;
            int r = idx >> 7, c = idx & 127;
            Ws[r * 128 + c] = W[(k0 + r) * HC + c];
        }
        __syncthreads();
#pragma unroll
        for (int k = 0; k < 32; k++) {
            float4 w4 = *(const float4*)&Ws[k * 128 + tx * 4];
#pragma unroll
            for (int r = 0; r < 8; r++) {
                float xv = Xs[(ty * 8 + r) * 32 + k];
                acc[r].x += xv * w4.x; acc[r].y += xv * w4.y;
                acc[r].z += xv * w4.z; acc[r].w += xv * w4.w;
            }
        }
        __syncthreads();
    }
#pragma unroll
    for (int r = 0; r < 8; r++) {
        int row = row0 + ty * 8 + r;
        if (row < NN) *(float4*)&out[row * HC + tx * 4] = acc[r];
    }
}

__global__ void count_kernel(const void* __restrict__ ei) {
    int e = blockIdx.x * blockDim.x + threadIdx.x;
    if (e >= ET) return;
    int src, dst;
    load_edge(ei, e, src, dst);
    atomicAdd(&g_deg[dst], 1);
}

// exclusive prefix scan of g_deg into g_off, one 1024-thread block
__global__ void scan_kernel() {
    __shared__ int s[1024];
    int tid = threadIdx.x;
    int running = 0;
    for (int base = 0; base < NN; base += 1024) {
        int v = (base + tid < NN) ? g_deg[base + tid] : 0;
        s[tid] = v;
        __syncthreads();
        for (int off = 1; off < 1024; off <<= 1) {
            int t = (tid >= off) ? s[tid - off] : 0;
            __syncthreads();
            s[tid] += t;
            __syncthreads();
        }
        if (base + tid < NN) g_off[base + tid] = running + s[tid] - v;
        running += s[1023];
        __syncthreads();
    }
    if (tid == 0) g_off[NN] = running;
}

__global__ void scatter_kernel(const void* __restrict__ ei) {
    int e = blockIdx.x * blockDim.x + threadIdx.x;
    if (e >= ET) return;
    int src, dst;
    load_edge(ei, e, src, dst);
    int pos = g_off[dst] + atomicAdd(&g_cur[dst], 1);
    g_ssrc[pos] = src;
    g_seid[pos] = e;
}

// ---- main: one warp per destination node ----
// lane l owns channels [4l, 4l+3]; head h = l>>3 (lane group of 8)
__global__ void gat_main_kernel(const float* __restrict__ att,
                                const float* __restrict__ bias,
                                float* __restrict__ out,
                                float* __restrict__ alpha) {
    int warp = (blockIdx.x * blockDim.x + threadIdx.x) >> 5;
    int lane = threadIdx.x & 31;
    if (warp >= NN) return;
    int dst = warp;

    float4 att4 = *(const float4*)&att[lane * 4];
    float4 xr4  = *(const float4*)&g_xr[dst * HC + lane * 4];
    int beg = g_off[dst], end = g_off[dst + 1];

    // pass A: online softmax (max + denom) over incident edges
    float m = -1e30f, den = 0.f;
    for (int i = beg; i < end; i++) {
        int s = g_ssrc[i];
        float4 a = *(const float4*)&g_xl[s * HC + lane * 4];
        float t0 = a.x + xr4.x, t1 = a.y + xr4.y, t2 = a.z + xr4.z, t3 = a.w + xr4.w;
        t0 = t0 > 0.f ? t0 : NEG_SLOPE * t0;
        t1 = t1 > 0.f ? t1 : NEG_SLOPE * t1;
        t2 = t2 > 0.f ? t2 : NEG_SLOPE * t2;
        t3 = t3 > 0.f ? t3 : NEG_SLOPE * t3;
        float p = t0 * att4.x + t1 * att4.y + t2 * att4.z + t3 * att4.w;
        p += __shfl_xor_sync(0xffffffffu, p, 1);
        p += __shfl_xor_sync(0xffffffffu, p, 2);
        p += __shfl_xor_sync(0xffffffffu, p, 4);
        float nm = fmaxf(m, p);
        den = den * __expf(m - nm) + __expf(p - nm);
        m = nm;
    }
    float invden = 1.0f / den;

    // pass C: alpha + weighted aggregation (p recomputed bitwise identically)
    float4 acc = make_float4(0.f, 0.f, 0.f, 0.f);
    int h = lane >> 3;
    for (int i = beg; i < end; i++) {
        int s   = g_ssrc[i];
        int eid = g_seid[i];
        float4 a = *(const float4*)&g_xl[s * HC + lane * 4];
        float t0 = a.x + xr4.x, t1 = a.y + xr4.y, t2 = a.z + xr4.z, t3 = a.w + xr4.w;
        t0 = t0 > 0.f ? t0 : NEG_SLOPE * t0;
        t1 = t1 > 0.f ? t1 : NEG_SLOPE * t1;
        t2 = t2 > 0.f ? t2 : NEG_SLOPE * t2;
        t3 = t3 > 0.f ? t3 : NEG_SLOPE * t3;
        float p = t0 * att4.x + t1 * att4.y + t2 * att4.z + t3 * att4.w;
        p += __shfl_xor_sync(0xffffffffu, p, 1);
        p += __shfl_xor_sync(0xffffffffu, p, 2);
        p += __shfl_xor_sync(0xffffffffu, p, 4);
        float al = __expf(p - m) * invden;
        if ((lane & 7) == 0 && alpha) alpha[eid * 4 + h] = al;
        acc.x += al * a.x; acc.y += al * a.y;
        acc.z += al * a.z; acc.w += al * a.w;
    }

    float4 b4 = *(const float4*)&bias[lane * 4];
    float4 o;
    o.x = fmaxf(acc.x + b4.x, 0.f);
    o.y = fmaxf(acc.y + b4.y, 0.f);
    o.z = fmaxf(acc.z + b4.z, 0.f);
    o.w = fmaxf(acc.w + b4.w, 0.f);
    *(float4*)&out[dst * HC + lane * 4] = o;
}

extern "C" void kernel_launch(void* const* d_in, const int* in_sizes, int n_in,
                              void* d_out, int out_size) {
    // identify inputs by element count (robust to metadata ordering)
    const float* x = nullptr; const void* ei = nullptr;
    const float* Wl = nullptr; const float* Wr = nullptr;
    const float* att = nullptr; const float* bias = nullptr;
    for (int i = 0; i < n_in; i++) {
        int s = in_sizes[i];
        if (s == NN * FIN)            x = (const float*)d_in[i];
        else if (s == 2 * EE)         ei = d_in[i];
        else if (s == FIN * HC) { if (!Wl) Wl = (const float*)d_in[i]; else Wr = (const float*)d_in[i]; }
        else if (s == HC)       { if (!att) att = (const float*)d_in[i]; else bias = (const float*)d_in[i]; }
    }

    float* out   = (float*)d_out;
    float* alpha = (out_size >= NN * HC + ET * 4) ? (out + NN * HC) : nullptr;

    probe_kernel<<<1, 32>>>((const int*)ei);
    zero_kernel<<<(NN + 255) / 256, 256>>>();
    gemm_kernel<<<(NN + 63) / 64, 256>>>(x, Wl, 0);
    gemm_kernel<<<(NN + 63) / 64, 256>>>(x, Wr, 1);
    count_kernel<<<(ET + 255) / 256, 256>>>(ei);
    scan_kernel<<<1, 1024>>>();
    scatter_kernel<<<(ET + 255) / 256, 256>>>(ei);
    gat_main_kernel<<<(NN * 32 + 255) / 256, 256>>>(att, bias, out, alpha);
}

// round 4
// speedup vs baseline: 1.4992x; 1.4992x over previous
#include <cuda_runtime.h>
#include <cstdint>

#define NN 50000
#define FIN 128
#define HC  128          // H*C = 4*32
#define EE  800000
#define ET  850000       // EE + NN self loops
#define NEG_SLOPE 0.2f

// ---- scratch (static device globals; no runtime allocation) ----
__device__ float g_xl[NN * HC];      // x @ Wl
__device__ float g_xr[NN * HC];      // x @ Wr
__device__ int   g_deg[NN];
__device__ int   g_cur[NN];
__device__ int   g_off[NN + 1];
__device__ int   g_ssrc[ET];         // src node per CSR slot
__device__ int   g_seid[ET];         // original edge id per CSR slot
__device__ int   g_is64;             // edge_index dtype flag
__device__ float g_logit[ET * 4];    // per-edge per-head raw attention logit
__device__ float g_sm[NN * 4];       // per-dst per-head softmax max
__device__ float g_sinv[NN * 4];     // per-dst per-head 1/denominator
__device__ int   g_bsum[64];         // block sums for scan
__device__ int   g_bsum_ex[65];      // exclusive-scanned block sums

// ---- probe: detect int64 vs int32 edge_index (parallel, 64 samples) ----
__global__ void probe_kernel(const int* __restrict__ ei32) {
    __shared__ int nz;
    if (threadIdx.x == 0) nz = 0;
    __syncthreads();
    if (threadIdx.x < 64) {
        long long k = ((long long)threadIdx.x * 1234567) % EE;
        int idx = (int)(2 * k + 1);                    // high word if int64
        if (ei32[idx] != 0) atomicAdd(&nz, 1);
    }
    __syncthreads();
    if (threadIdx.x == 0) g_is64 = (nz == 0) ? 1 : 0;
}

__device__ __forceinline__ void load_edge(const void* ei, int e, int& src, int& dst) {
    if (e >= EE) { src = dst = e - EE; return; }
    if (g_is64) {
        const long long* p = (const long long*)ei;
        src = (int)p[e]; dst = (int)p[EE + e];
    } else {
        const int* p = (const int*)ei;
        src = p[e]; dst = p[EE + e];
    }
    src = min(max(src, 0), NN - 1);
    dst = min(max(dst, 0), NN - 1);
}

__global__ void zero_kernel() {
    int i = blockIdx.x * blockDim.x + threadIdx.x;
    if (i < NN) { g_deg[i] = 0; g_cur[i] = 0; }
}

// ==================================================================
// Fused 3xTF32 tensor-core GEMM: [NN,128] @ [128, 128|128] -> g_xl,g_xr
// Block: 128 rows x 256 cols, 512 threads = 16 warps (4m x 4n).
// Warp tile 32x64 -> 2 mtiles x 8 ntiles of m16n8k8.
// 3xTF32: acc += lo_a*hi_b + hi_a*lo_b + hi_a*hi_b  (fp32-class accuracy)
// ==================================================================
#define LDA 20   // 16 + 4 pad  -> (20g+k)%32 distinct for g<8,k<4
#define LDB 264  // 256 + 8 pad -> (8g+col)%32 distinct

__device__ __forceinline__ uint32_t f2tf(float f) {
    uint32_t u;
    asm("cvt.rna.tf32.f32 %0, %1;" : "=r"(u) : "f"(f));
    return u;
}
__device__ __forceinline__ void split_tf(float v, uint32_t& hi, uint32_t& lo) {
    hi = f2tf(v);
    lo = f2tf(v - __uint_as_float(hi));
}
__device__ __forceinline__ void mma_tf32(float* c, const uint32_t* a, const uint32_t* b) {
    asm volatile(
        "mma.sync.aligned.m16n8k8.row.col.f32.tf32.tf32.f32 "
        "{%0,%1,%2,%3},{%4,%5,%6,%7},{%8,%9},{%0,%1,%2,%3};"
        : "+f"(c[0]), "+f"(c[1]), "+f"(c[2]), "+f"(c[3])
        : "r"(a[0]), "r"(a[1]), "r"(a[2]), "r"(a[3]), "r"(b[0]), "r"(b[1]));
}

__global__ __launch_bounds__(512, 1)
void gemm_fused_kernel(const float* __restrict__ x,
                       const float* __restrict__ Wl,
                       const float* __restrict__ Wr) {
    __shared__ float As[128 * LDA];
    __shared__ float Bs[16 * LDB];

    int tid  = threadIdx.x;
    int wid  = tid >> 5;
    int lane = tid & 31;
    int wm   = wid & 3;        // warp m index (0..3) -> 32 rows
    int wn   = wid >> 2;       // warp n index (0..3) -> 64 cols
    int g    = lane >> 2;      // group id 0..7
    int t4   = lane & 3;       // thread in group 0..3
    int row0 = blockIdx.x * 128;

    float acc[2][8][4];
#pragma unroll
    for (int mt = 0; mt < 2; mt++)
#pragma unroll
        for (int nt = 0; nt < 8; nt++)
#pragma unroll
            for (int i = 0; i < 4; i++) acc[mt][nt][i] = 0.f;

    for (int kc = 0; kc < 8; kc++) {        // 8 chunks of K=16
        // load A: 128 rows x 16 cols = 512 float4, 1 per thread
        {
            int r = tid >> 2, c4 = tid & 3;
            int rr = row0 + r; if (rr >= NN) rr = NN - 1;
            float4 v = *(const float4*)&x[rr * FIN + kc * 16 + c4 * 4];
            *(float4*)&As[r * LDA + c4 * 4] = v;
        }
        // load B: 16 rows x 256 cols = 1024 float4, 2 per thread
#pragma unroll
        for (int i = 0; i < 2; i++) {
            int idx = i * 512 + tid;
            int r = idx >> 6, c4 = idx & 63;
            int col = c4 * 4;
            const float* Wp = (col < 128) ? &Wl[(kc * 16 + r) * HC + col]
                                          : &Wr[(kc * 16 + r) * HC + col - 128];
            *(float4*)&Bs[r * LDB + col] = *(const float4*)Wp;
        }
        __syncthreads();

#pragma unroll
        for (int ks = 0; ks < 2; ks++) {    // 2 k-steps of 8
            // A fragments (2 mtiles), hi/lo
            uint32_t ah[2][4], al[2][4];
#pragma unroll
            for (int mt = 0; mt < 2; mt++) {
                int rb = wm * 32 + mt * 16 + g;
                int kb = ks * 8 + t4;
                split_tf(As[rb * LDA + kb],           ah[mt][0], al[mt][0]);
                split_tf(As[(rb + 8) * LDA + kb],     ah[mt][1], al[mt][1]);
                split_tf(As[rb * LDA + kb + 4],       ah[mt][2], al[mt][2]);
                split_tf(As[(rb + 8) * LDA + kb + 4], ah[mt][3], al[mt][3]);
            }
#pragma unroll
            for (int nt = 0; nt < 8; nt++) {
                int cb = wn * 64 + nt * 8 + g;
                int kb = ks * 8 + t4;
                uint32_t bh[2], bl[2];
                split_tf(Bs[kb * LDB + cb],       bh[0], bl[0]);
                split_tf(Bs[(kb + 4) * LDB + cb], bh[1], bl[1]);
#pragma unroll
                for (int mt = 0; mt < 2; mt++) {
                    mma_tf32(acc[mt][nt], al[mt], bh);   // small terms first
                    mma_tf32(acc[mt][nt], ah[mt], bl);
                    mma_tf32(acc[mt][nt], ah[mt], bh);
                }
            }
        }
        __syncthreads();
    }

    // epilogue
#pragma unroll
    for (int mt = 0; mt < 2; mt++) {
#pragma unroll
        for (int nt = 0; nt < 8; nt++) {
            int r0 = row0 + wm * 32 + mt * 16 + g;
            int c0 = wn * 64 + nt * 8 + t4 * 2;
            float* dst = (c0 < 128) ? g_xl : g_xr;
            int cc = c0 & 127;
            if (r0 < NN)     *(float2*)&dst[r0 * HC + cc]       = make_float2(acc[mt][nt][0], acc[mt][nt][1]);
            if (r0 + 8 < NN) *(float2*)&dst[(r0 + 8) * HC + cc] = make_float2(acc[mt][nt][2], acc[mt][nt][3]);
        }
    }
}

// ==================================================================
// CSR build
// ==================================================================
__global__ void count_kernel(const void* __restrict__ ei) {
    int e = blockIdx.x * blockDim.x + threadIdx.x;
    if (e >= ET) return;
    int src, dst;
    load_edge(ei, e, src, dst);
    atomicAdd(&g_deg[dst], 1);
}

// two-level scan: per-block exclusive scan (1024 elems/block)
__global__ void scan1_kernel() {
    __shared__ int wsum[32];
    int tid = threadIdx.x, lane = tid & 31, w = tid >> 5;
    int i = blockIdx.x * 1024 + tid;
    int v = (i < NN) ? g_deg[i] : 0;
    // warp inclusive scan
    int s = v;
#pragma unroll
    for (int o = 1; o < 32; o <<= 1) {
        int t = __shfl_up_sync(0xffffffffu, s, o);
        if (lane >= o) s += t;
    }
    if (lane == 31) wsum[w] = s;
    __syncthreads();
    if (w == 0) {
        int ws = (lane < 32) ? wsum[lane] : 0;
#pragma unroll
        for (int o = 1; o < 32; o <<= 1) {
            int t = __shfl_up_sync(0xffffffffu, ws, o);
            if (lane >= o) ws += t;
        }
        wsum[lane] = ws;
    }
    __syncthreads();
    int base = (w > 0) ? wsum[w - 1] : 0;
    if (i < NN) g_off[i] = base + s - v;          // exclusive within block
    if (tid == 1023) g_bsum[blockIdx.x] = base + s;
}

__global__ void scan2_kernel(int nblocks) {
    int lane = threadIdx.x;
    int v = (lane < nblocks) ? g_bsum[lane] : 0;
    int s = v;
#pragma unroll
    for (int o = 1; o < 64; o <<= 1) {
        int t = __shfl_up_sync(0xffffffffu, s, o);   // 64 > warp; do via smem
        (void)t;
        break;
    }
    // simple shared-memory scan (nblocks <= 64)
    __shared__ int sh[65];
    sh[lane] = v;
    __syncthreads();
    for (int o = 1; o < 64; o <<= 1) {
        int t = (lane >= o) ? sh[lane - o] : 0;
        __syncthreads();
        sh[lane] += t;
        __syncthreads();
    }
    g_bsum_ex[lane] = sh[lane] - v;                  // exclusive
    if (lane == nblocks - 1) g_bsum_ex[64] = sh[lane];   // total
}

__global__ void scan3_kernel() {
    int i = blockIdx.x * blockDim.x + threadIdx.x;
    if (i < NN) g_off[i] += g_bsum_ex[i >> 10];
    if (i == 0) g_off[NN] = g_bsum_ex[64];
}

__global__ void scatter_kernel(const void* __restrict__ ei) {
    int e = blockIdx.x * blockDim.x + threadIdx.x;
    if (e >= ET) return;
    int src, dst;
    load_edge(ei, e, src, dst);
    int pos = g_off[dst] + atomicAdd(&g_cur[dst], 1);
    g_ssrc[pos] = src;
    g_seid[pos] = e;
}

// ==================================================================
// main: one warp per dst, SINGLE pass with online softmax rescaling.
// lane l owns channels [4l,4l+3]; head h = l>>3 (group of 8 lanes)
// Stashes logits per edge; per-dst (m, 1/den) for the alpha kernel.
// ==================================================================
__global__ void gat_main_kernel(const float* __restrict__ att,
                                const float* __restrict__ bias,
                                float* __restrict__ out) {
    int warp = (blockIdx.x * blockDim.x + threadIdx.x) >> 5;
    int lane = threadIdx.x & 31;
    if (warp >= NN) return;
    int dst = warp;

    float4 att4 = *(const float4*)&att[lane * 4];
    float4 xr4  = *(const float4*)&g_xr[dst * HC + lane * 4];
    int beg = g_off[dst], end = g_off[dst + 1];
    int h = lane >> 3;

    float m = -1e30f, den = 0.f;
    float4 acc = make_float4(0.f, 0.f, 0.f, 0.f);
    for (int i = beg; i < end; i++) {
        int s   = g_ssrc[i];
        int eid = g_seid[i];
        float4 a = *(const float4*)&g_xl[s * HC + lane * 4];
        float t0 = a.x + xr4.x, t1 = a.y + xr4.y, t2 = a.z + xr4.z, t3 = a.w + xr4.w;
        t0 = t0 > 0.f ? t0 : NEG_SLOPE * t0;
        t1 = t1 > 0.f ? t1 : NEG_SLOPE * t1;
        t2 = t2 > 0.f ? t2 : NEG_SLOPE * t2;
        t3 = t3 > 0.f ? t3 : NEG_SLOPE * t3;
        float p = t0 * att4.x + t1 * att4.y + t2 * att4.z + t3 * att4.w;
        p += __shfl_xor_sync(0xffffffffu, p, 1);
        p += __shfl_xor_sync(0xffffffffu, p, 2);
        p += __shfl_xor_sync(0xffffffffu, p, 4);
        if ((lane & 7) == 0) g_logit[eid * 4 + h] = p;
        float nm = fmaxf(m, p);
        float sc = __expf(m - nm);
        float e  = __expf(p - nm);
        den = den * sc + e;
        m = nm;
        acc.x = acc.x * sc + e * a.x;
        acc.y = acc.y * sc + e * a.y;
        acc.z = acc.z * sc + e * a.z;
        acc.w = acc.w * sc + e * a.w;
    }
    float invden = 1.0f / den;
    if ((lane & 7) == 0) {
        g_sm[dst * 4 + h]   = m;
        g_sinv[dst * 4 + h] = invden;
    }

    float4 b4 = *(const float4*)&bias[lane * 4];
    float4 o;
    o.x = fmaxf(acc.x * invden + b4.x, 0.f);
    o.y = fmaxf(acc.y * invden + b4.y, 0.f);
    o.z = fmaxf(acc.z * invden + b4.z, 0.f);
    o.w = fmaxf(acc.w * invden + b4.w, 0.f);
    *(float4*)&out[dst * HC + lane * 4] = o;
}

// edge-parallel alpha: alpha[e][h] = exp(logit - m[dst][h]) * inv[dst][h]
__global__ void alpha_kernel(const void* __restrict__ ei,
                             float* __restrict__ alpha) {
    int e = blockIdx.x * blockDim.x + threadIdx.x;
    if (e >= ET) return;
    int src, dst;
    load_edge(ei, e, src, dst);
    float4 l4 = *(const float4*)&g_logit[e * 4];
    float4 m4 = *(const float4*)&g_sm[dst * 4];
    float4 i4 = *(const float4*)&g_sinv[dst * 4];
    float4 a4;
    a4.x = __expf(l4.x - m4.x) * i4.x;
    a4.y = __expf(l4.y - m4.y) * i4.y;
    a4.z = __expf(l4.z - m4.z) * i4.z;
    a4.w = __expf(l4.w - m4.w) * i4.w;
    *(float4*)&alpha[e * 4] = a4;
}

extern "C" void kernel_launch(void* const* d_in, const int* in_sizes, int n_in,
                              void* d_out, int out_size) {
    // identify inputs by element count (robust to metadata ordering)
    const float* x = nullptr; const void* ei = nullptr;
    const float* Wl = nullptr; const float* Wr = nullptr;
    const float* att = nullptr; const float* bias = nullptr;
    for (int i = 0; i < n_in; i++) {
        int s = in_sizes[i];
        if (s == NN * FIN)            x = (const float*)d_in[i];
        else if (s == 2 * EE)         ei = d_in[i];
        else if (s == FIN * HC) { if (!Wl) Wl = (const float*)d_in[i]; else Wr = (const float*)d_in[i]; }
        else if (s == HC)       { if (!att) att = (const float*)d_in[i]; else bias = (const float*)d_in[i]; }
    }

    float* out   = (float*)d_out;
    float* alpha = (out_size >= NN * HC + ET * 4) ? (out + NN * HC) : nullptr;

    probe_kernel<<<1, 64>>>((const int*)ei);
    zero_kernel<<<(NN + 255) / 256, 256>>>();
    gemm_fused_kernel<<<(NN + 127) / 128, 512>>>(x, Wl, Wr);
    count_kernel<<<(ET + 255) / 256, 256>>>(ei);
    int nblk = (NN + 1023) / 1024;
    scan1_kernel<<<nblk, 1024>>>();
    scan2_kernel<<<1, 64>>>(nblk);
    scan3_kernel<<<(NN + 1023) / 1024, 1024>>>();
    scatter_kernel<<<(ET + 255) / 256, 256>>>(ei);
    gat_main_kernel<<<(NN * 32 + 255) / 256, 256>>>(att, bias, out);
    if (alpha) alpha_kernel<<<(ET + 255) / 256, 256>>>(ei, alpha);
}